// round 16
// baseline (speedup 1.0000x reference)
#include <cuda_runtime.h>
#include <cuda_fp16.h>
#include <math.h>
#include <stdint.h>

#define DTC 0.001
#define Pdim 1024
#define Hdim 256
#define Ldim 16384
#define NKC  16             // K chunks of 64 (K = 1024)
#define STAGE_BYTES 81920   // Ar 16K | Ai 16K | Ami 16K | Vr 16K | Vi 16K
#define WSCALE 65536.0f
#define INV_WSCALE 1.52587890625e-05f

// ---------------------------------------------------------------------------
// Device-global scratch (allocation-free rule)
// ---------------------------------------------------------------------------
// Power table: g_pow[p][j] = A_bar[p]^(2^j), j=0..13 (fp32, computed in fp64)
__device__ __align__(16) float2 g_pow[Pdim * 16];
// A planes [0=Wr, 1=Wi, 2=-Wi][kc(16)][m=h(256)][kk(64)] fp16, scaled 2^16
__device__ __align__(128) __half g_A[3][(size_t)16 * 256 * 64];

// ---------------------------------------------------------------------------
// helpers
// ---------------------------------------------------------------------------
__device__ __forceinline__ uint32_t s2u(const void* p) {
    uint32_t a;
    asm("{ .reg .u64 t; cvta.to.shared.u64 t, %1; cvt.u32.u64 %0, t; }"
        : "=r"(a) : "l"(p));
    return a;
}

template <int DOFF, int SOFF>
__device__ __forceinline__ void cpa(uint32_t dst, const char* src) {
    asm volatile("cp.async.cg.shared.global [%0+%2], [%1+%3], 16;"
                 :: "r"(dst), "l"(src), "n"(DOFF), "n"(SOFF) : "memory");
}

template <int OFF>
__device__ __forceinline__ void ldm4(uint32_t* r, uint32_t a) {
    asm volatile("ldmatrix.sync.aligned.m8n8.x4.shared.b16 {%0,%1,%2,%3}, [%4+%5];"
                 : "=r"(r[0]), "=r"(r[1]), "=r"(r[2]), "=r"(r[3])
                 : "r"(a), "n"(OFF));
}

__device__ __forceinline__ void mma16816(float* d, const uint32_t* a,
                                         uint32_t b0, uint32_t b1) {
    asm volatile(
        "mma.sync.aligned.m16n8k16.row.col.f32.f16.f16.f32 "
        "{%0,%1,%2,%3}, {%4,%5,%6,%7}, {%8,%9}, {%0,%1,%2,%3};"
        : "+f"(d[0]), "+f"(d[1]), "+f"(d[2]), "+f"(d[3])
        : "r"(a[0]), "r"(a[1]), "r"(a[2]), "r"(a[3]), "r"(b0), "r"(b1));
}

// fp64 Taylor for A_bar = exp((ar + i*ai)*dt), tiny args.
__device__ __forceinline__ void abar_taylor(float ar, float ai,
                                            float& abr, float& abi) {
    double y  = (double)ar * DTC;
    double th = (double)ai * DTC;
    double e = 1.0 + y * (1.0 + y * (0.5 + y * (1.0 / 6.0 + y * (1.0 / 24.0))));
    double t2 = th * th;
    double c = 1.0 + t2 * (-0.5 + t2 * (1.0 / 24.0));
    double s = th * (1.0 + t2 * (-1.0 / 6.0 + t2 * (1.0 / 120.0)));
    abr = (float)(e * c);
    abi = (float)(e * s);
}

// ---------------------------------------------------------------------------
// k_prep: blocks 0..31 build the power table (fp64 squarings, fp32 levels);
// blocks 32..95 = setupA (R15 scheme, coalesced, per-p cf computed once).
// ---------------------------------------------------------------------------
__global__ void k_prep(const float* __restrict__ Ain,
                       const float* __restrict__ B,
                       const float* __restrict__ C) {
    if (blockIdx.x < 32) {
        int p = blockIdx.x * 32 + threadIdx.x;
        if (threadIdx.x >= 32 || p >= Pdim) return;
        float ar = Ain[2 * p], ai = Ain[2 * p + 1];
        float abr, abi;
        abar_taylor(ar, ai, abr, abi);
        double dr = (double)abr, di = (double)abi;
        #pragma unroll
        for (int j = 0; j < 14; j++) {
            g_pow[p * 16 + j] = make_float2((float)dr, (float)di);
            double nr = dr * dr - di * di;
            double ni = 2.0 * dr * di;
            dr = nr; di = ni;
        }
    } else {
        __shared__ float2 scf[64];
        int b  = blockIdx.x - 32;       // 0..63
        int kc = b >> 2;                // 0..15
        int h0 = (b & 3) * 64;
        int t  = threadIdx.x;

        if (t < 64) {
            int p = kc * 64 + t;
            float ar = Ain[2 * p], ai = Ain[2 * p + 1];
            float abr, abi;
            abar_taylor(ar, ai, abr, abi);
            float nr = abr - 1.0f, ni = abi;       // Sterbenz-exact
            float den = ar * ar + ai * ai;
            scf[t] = make_float2((nr * ar + ni * ai) / den,
                                 (ni * ar - nr * ai) / den);
        }
        __syncthreads();

        int kk  = t & 63;
        int hh0 = t >> 6;               // 0..3
        int p   = kc * 64 + kk;
        float2 cf = scf[kk];

        #pragma unroll 4
        for (int i = 0; i < 16; i++) {
            int h = h0 + i * 4 + hh0;
            float br = B[(p * Hdim + h) * 2], bi = B[(p * Hdim + h) * 2 + 1];
            float bbr = cf.x * br - cf.y * bi;
            float bbi = cf.x * bi + cf.y * br;
            float cr = C[(h * Pdim + p) * 2], ci = C[(h * Pdim + p) * 2 + 1];
            float wr = (cr * bbr - ci * bbi) * WSCALE;
            float wi = (cr * bbi + ci * bbr) * WSCALE;

            size_t o = ((size_t)kc * 256 + h) * 64 + kk;
            g_A[0][o] = __float2half_rn(wr);
            g_A[1][o] = __float2half_rn(wi);
            g_A[2][o] = __float2half_rn(-wi);
        }
    }
}

// ---------------------------------------------------------------------------
// k_gemm: fused 4-mult complex GEMM with IN-KERNEL V generation (no g_B).
// Per chunk, each thread generates its (p-pair, 8-l-run) slice of the B tile
// directly into the stage's Vr/Vi smem planes: seed = product of fp64-exact
// power-table entries selected by the bits of l0 (n0 bits uniform, lrun bits
// predicated), then an 8-step fp32 recurrence with half2 swizzled stores.
// MMA mainloop identical to R15.
// ---------------------------------------------------------------------------
__global__ __launch_bounds__(512, 1) void k_gemm(float* __restrict__ out) {
    extern __shared__ char smp[];
    const int tid  = threadIdx.x;
    const int lane = tid & 31;
    const int wid  = tid >> 5;
    const int wm   = wid >> 2;            // 0..3
    const int wn   = wid & 3;             // 0..3
    const int m0   = blockIdx.x * 128;
    const int n0   = blockIdx.y * 128;
    const uint32_t sb = s2u(smp);

    float accR[2][4][4], accI[2][4][4];
    #pragma unroll
    for (int i = 0; i < 2; i++)
        #pragma unroll
        for (int j = 0; j < 4; j++)
            #pragma unroll
            for (int t = 0; t < 4; t++) { accR[i][j][t] = 0.0f; accI[i][j][t] = 0.0f; }

    // ---- A-plane cp.async mapping ----
    const int crow = tid >> 3;
    const int ccol = tid & 7;
    const uint32_t dA0 = sb + crow * 128 + ((ccol ^ (crow & 7)) << 4);
    const uint32_t dA1 = dA0 + STAGE_BYTES;
    const char* pA = (const char*)g_A[0] +
                     (((size_t)(m0 + crow) * 64 + ccol * 8) * 2);

    auto issueA = [&](uint32_t dA) {
        cpa<0,         0>(dA, pA);                 // Wr
        cpa<8192,   8192>(dA, pA);
        cpa<16384,     0>(dA, pA + 524288);        // Wi
        cpa<24576,  8192>(dA, pA + 524288);
        cpa<32768,     0>(dA, pA + 1048576);       // -Wi
        cpa<40960,  8192>(dA, pA + 1048576);
        asm volatile("cp.async.commit_group;" ::: "memory");
        pA += 32768;
    };

    // ---- V generation constants ----
    const int kp   = tid & 31;            // p-pair: kk = 2*kp
    const int lrun = tid >> 5;            // 0..15, l = lrun*8 + q
    const int nb   = n0 >> 7;             // n0 bits (j = 7..13)

    auto genB = [&](int kc, int s) {
        int p0 = kc * 64 + 2 * kp;
        const float2* P0 = g_pow + p0 * 16;
        const float2* P1 = P0 + 16;
        float s0r = 1.0f, s0i = 0.0f, s1r = 1.0f, s1i = 0.0f;
        #pragma unroll
        for (int j = 0; j < 7; j++) {
            if ((nb >> j) & 1) {               // uniform per CTA
                float2 q0 = P0[j + 7], q1 = P1[j + 7];
                float t0r = s0r * q0.x - s0i * q0.y;
                float t0i = s0r * q0.y + s0i * q0.x;
                float t1r = s1r * q1.x - s1i * q1.y;
                float t1i = s1r * q1.y + s1i * q1.x;
                s0r = t0r; s0i = t0i; s1r = t1r; s1i = t1i;
            }
        }
        #pragma unroll
        for (int j = 0; j < 4; j++) {
            if ((lrun >> j) & 1) {             // predicated
                float2 q0 = P0[j + 3], q1 = P1[j + 3];
                float t0r = s0r * q0.x - s0i * q0.y;
                float t0i = s0r * q0.y + s0i * q0.x;
                float t1r = s1r * q1.x - s1i * q1.y;
                float t1i = s1r * q1.y + s1i * q1.x;
                s0r = t0r; s0i = t0i; s1r = t1r; s1i = t1i;
            }
        }
        float2 a0 = P0[0], a1 = P1[0];         // A_bar step
        char* vr = smp + s * STAGE_BYTES + 49152;
        char* vi = smp + s * STAGE_BYTES + 65536;
        int l = lrun * 8;
        #pragma unroll
        for (int q = 0; q < 8; q++, l++) {
            uint32_t bo = (uint32_t)(l * 128 + kp * 4);
            uint32_t sw = bo ^ ((bo >> 3) & 0x70);
            *(__half2*)(vr + sw) = __floats2half2_rn(s0r, s1r);
            *(__half2*)(vi + sw) = __floats2half2_rn(s0i, s1i);
            float t0r = s0r * a0.x - s0i * a0.y;
            float t0i = s0r * a0.y + s0i * a0.x;
            float t1r = s1r * a1.x - s1i * a1.y;
            float t1i = s1r * a1.y + s1i * a1.x;
            s0r = t0r; s0i = t0i; s1r = t1r; s1i = t1i;
        }
    };

    // ---- ldmatrix offsets (loop-invariant) ----
    const int r15 = lane & 15, h16 = lane >> 4;
    const int rA = wm * 32 + r15;
    const int rB = wn * 32 + r15;
    uint32_t oA[4], oB[4];
    #pragma unroll
    for (int ks = 0; ks < 4; ks++) {
        const int cc = 2 * ks + h16;
        oA[ks] = (uint32_t)(rA * 128 + ((cc ^ (rA & 7)) << 4));
        oB[ks] = (uint32_t)(rB * 128 + ((cc ^ (rB & 7)) << 4)) + 49152u;
    }

    issueA(dA0);
    genB(0, 0);

    #pragma unroll 2
    for (int k = 0; k < NKC; k++) {
        const uint32_t stage = sb + (uint32_t)((k & 1) * STAGE_BYTES);
        if (k + 1 < NKC) {
            issueA((k & 1) ? dA0 : dA1);
            asm volatile("cp.async.wait_group 1;" ::: "memory");
        } else {
            asm volatile("cp.async.wait_group 0;" ::: "memory");
        }
        __syncthreads();
        // stage^1's B planes were consumed at iter k-1 -> safe to refill now.
        if (k + 1 < NKC) genB(k + 1, (k & 1) ^ 1);

        #pragma unroll
        for (int ks = 0; ks < 4; ks++) {
            const uint32_t aAddr = stage + oA[ks];
            const uint32_t bAddr = stage + oB[ks];

            uint32_t ar0[4], ar1[4], ax0[4], ax1[4], b0[4], b1[4];
            // phase 1: Wr, Wi vs Vr
            ldm4<0>     (ar0, aAddr);
            ldm4<2048>  (ar1, aAddr);
            ldm4<16384> (ax0, aAddr);
            ldm4<18432> (ax1, aAddr);
            ldm4<0>     (b0, bAddr);
            ldm4<2048>  (b1, bAddr);

            mma16816(accR[0][0], ar0, b0[0], b0[2]);
            mma16816(accR[0][1], ar0, b0[1], b0[3]);
            mma16816(accR[0][2], ar0, b1[0], b1[2]);
            mma16816(accR[0][3], ar0, b1[1], b1[3]);
            mma16816(accR[1][0], ar1, b0[0], b0[2]);
            mma16816(accR[1][1], ar1, b0[1], b0[3]);
            mma16816(accR[1][2], ar1, b1[0], b1[2]);
            mma16816(accR[1][3], ar1, b1[1], b1[3]);
            mma16816(accI[0][0], ax0, b0[0], b0[2]);
            mma16816(accI[0][1], ax0, b0[1], b0[3]);
            mma16816(accI[0][2], ax0, b1[0], b1[2]);
            mma16816(accI[0][3], ax0, b1[1], b1[3]);
            mma16816(accI[1][0], ax1, b0[0], b0[2]);
            mma16816(accI[1][1], ax1, b0[1], b0[3]);
            mma16816(accI[1][2], ax1, b1[0], b1[2]);
            mma16816(accI[1][3], ax1, b1[1], b1[3]);

            // phase 2: reuse slots -> -Wi and Vi
            ldm4<32768> (ax0, aAddr);
            ldm4<34816> (ax1, aAddr);
            ldm4<16384> (b0, bAddr);
            ldm4<18432> (b1, bAddr);

            mma16816(accI[0][0], ar0, b0[0], b0[2]);
            mma16816(accI[0][1], ar0, b0[1], b0[3]);
            mma16816(accI[0][2], ar0, b1[0], b1[2]);
            mma16816(accI[0][3], ar0, b1[1], b1[3]);
            mma16816(accI[1][0], ar1, b0[0], b0[2]);
            mma16816(accI[1][1], ar1, b0[1], b0[3]);
            mma16816(accI[1][2], ar1, b1[0], b1[2]);
            mma16816(accI[1][3], ar1, b1[1], b1[3]);
            mma16816(accR[0][0], ax0, b0[0], b0[2]);
            mma16816(accR[0][1], ax0, b0[1], b0[3]);
            mma16816(accR[0][2], ax0, b1[0], b1[2]);
            mma16816(accR[0][3], ax0, b1[1], b1[3]);
            mma16816(accR[1][0], ax1, b0[0], b0[2]);
            mma16816(accR[1][1], ax1, b0[1], b0[3]);
            mma16816(accR[1][2], ax1, b1[0], b1[2]);
            mma16816(accR[1][3], ax1, b1[1], b1[3]);
        }
        __syncthreads();
    }

    // Epilogue: interleaved (re, im) float4 writes, n == l.
    const int mrow = lane >> 2, ncol = (lane & 3) * 2;
    #pragma unroll
    for (int im = 0; im < 2; im++) {
        int m = m0 + wm * 32 + im * 16 + mrow;
        #pragma unroll
        for (int jn = 0; jn < 4; jn++) {
            int n = n0 + wn * 32 + jn * 8 + ncol;
            float* p = out + ((size_t)m * Ldim + n) * 2;
            *(float4*)p = make_float4(accR[im][jn][0] * INV_WSCALE,
                                      accI[im][jn][0] * INV_WSCALE,
                                      accR[im][jn][1] * INV_WSCALE,
                                      accI[im][jn][1] * INV_WSCALE);
            *(float4*)(p + (size_t)16 * Ldim) = make_float4(
                                      accR[im][jn][2] * INV_WSCALE,
                                      accI[im][jn][2] * INV_WSCALE,
                                      accR[im][jn][3] * INV_WSCALE,
                                      accI[im][jn][3] * INV_WSCALE);
        }
    }
}

// ---------------------------------------------------------------------------
extern "C" void kernel_launch(void* const* d_in, const int* in_sizes, int n_in,
                              void* d_out, int out_size) {
    const float* A = (const float*)d_in[0];
    const float* B = (const float*)d_in[1];
    const float* C = (const float*)d_in[2];

    cudaFuncSetAttribute(k_gemm, cudaFuncAttributeMaxDynamicSharedMemorySize, 163840);

    k_prep<<<96, 256>>>(A, B, C);
    k_gemm<<<dim3(2, 128), 512, 163840>>>((float*)d_out);
}

// round 17
// speedup vs baseline: 2.0206x; 2.0206x over previous
#include <cuda_runtime.h>
#include <cuda_fp16.h>
#include <math.h>
#include <stdint.h>

#define DTC 0.001
#define Pdim 1024
#define Hdim 256
#define Ldim 16384
#define NKC  16             // K chunks of 64 (K = 1024)
#define STAGE_BYTES 81920   // Ar 16K | Ai 16K | Ami 16K | Vr 16K | Vi 16K
#define WSCALE 65536.0f
#define INV_WSCALE 1.52587890625e-05f

// ---------------------------------------------------------------------------
// Device-global scratch (allocation-free rule)
// ---------------------------------------------------------------------------
// A planes [0=Wr, 1=Wi, 2=-Wi][kc(16)][m=h(256)][kk(64)] fp16, scaled 2^16
__device__ __align__(128) __half g_A[3][(size_t)16 * 256 * 64];
// B planes [0=Vr, 1=Vi][kc(16)][n=l(16384)][kk(64)] fp16; plane stride 33554432 B
__device__ __align__(128) __half g_B[2][(size_t)16 * 16384 * 64];

// ---------------------------------------------------------------------------
// helpers
// ---------------------------------------------------------------------------
__device__ __forceinline__ uint32_t s2u(const void* p) {
    uint32_t a;
    asm("{ .reg .u64 t; cvta.to.shared.u64 t, %1; cvt.u32.u64 %0, t; }"
        : "=r"(a) : "l"(p));
    return a;
}

template <int DOFF, int SOFF>
__device__ __forceinline__ void cpa(uint32_t dst, const char* src) {
    asm volatile("cp.async.cg.shared.global [%0+%2], [%1+%3], 16;"
                 :: "r"(dst), "l"(src), "n"(DOFF), "n"(SOFF) : "memory");
}

template <int OFF>
__device__ __forceinline__ void ldm4(uint32_t* r, uint32_t a) {
    asm volatile("ldmatrix.sync.aligned.m8n8.x4.shared.b16 {%0,%1,%2,%3}, [%4+%5];"
                 : "=r"(r[0]), "=r"(r[1]), "=r"(r[2]), "=r"(r[3])
                 : "r"(a), "n"(OFF));
}

__device__ __forceinline__ void mma16816(float* d, const uint32_t* a,
                                         uint32_t b0, uint32_t b1) {
    asm volatile(
        "mma.sync.aligned.m16n8k16.row.col.f32.f16.f16.f32 "
        "{%0,%1,%2,%3}, {%4,%5,%6,%7}, {%8,%9}, {%0,%1,%2,%3};"
        : "+f"(d[0]), "+f"(d[1]), "+f"(d[2]), "+f"(d[3])
        : "r"(a[0]), "r"(a[1]), "r"(a[2]), "r"(a[3]), "r"(b0), "r"(b1));
}

// fp64 Taylor for A_bar = exp((ar + i*ai)*dt), tiny args; matches the
// reference's fp32-rounded A_bar to ~2^-50 before rounding.
__device__ __forceinline__ void abar_taylor(float ar, float ai,
                                            float& abr, float& abi) {
    double y  = (double)ar * DTC;                 // [-5e-4, -1e-5]
    double th = (double)ai * DTC;                 // [-3.15e-3, 3.15e-3]
    double e = 1.0 + y * (1.0 + y * (0.5 + y * (1.0 / 6.0 + y * (1.0 / 24.0))));
    double t2 = th * th;
    double c = 1.0 + t2 * (-0.5 + t2 * (1.0 / 24.0));
    double s = th * (1.0 + t2 * (-1.0 / 6.0 + t2 * (1.0 / 120.0)));
    abr = (float)(e * c);
    abi = (float)(e * s);
}

// ---------------------------------------------------------------------------
// k_fill: blocks 0..127 = genB; blocks 128..191 = setupA. No k_pre kernel:
// each consumer computes its per-p constants inline.
//
// genB: lane owns adjacent p-pair. A_bar via inline fp64 Taylor; A256 via
// fp32 squarings (err <= 8 ulp, ^seg<=63 -> <=3e-5 on seeds, << fp16 eps);
// seed = A256^seg by fp32 binary exponentiation; fp32 recurrence over the
// 256-l segment; half2 stores -> 128 B coalesced per warp per plane.
//
// setupA: 64 blocks, each (kc = b>>2, h-quadrant = b&3). Phase 1: threads
// 0..63 compute cf(p) = (A_bar-1)/Ac ONCE per p (fp64 Taylor; abr-1 is
// Sterbenz-exact, matching the reference's cancellation) into smem.
// Phase 2: 16 iterations cover 64p x 64h; B reads + plane stores coalesced.
// ---------------------------------------------------------------------------
__global__ void k_fill(const float* __restrict__ Ain,
                       const float* __restrict__ B,
                       const float* __restrict__ C) {
    if (blockIdx.x < 128) {
        int wid = blockIdx.x * 8 + (threadIdx.x >> 5);   // 0..1023
        int lane = threadIdx.x & 31;
        int pg  = wid & 15;             // 16 groups of 64 p (== kc chunk)
        int seg = wid >> 4;             // 0..63
        int p0 = pg * 64 + 2 * lane;

        float4 av = ((const float4*)Ain)[p0 >> 1];   // (ar0, ai0, ar1, ai1)
        float ab0x, ab0y, ab1x, ab1y;
        abar_taylor(av.x, av.y, ab0x, ab0y);
        abar_taylor(av.z, av.w, ab1x, ab1y);

        // A256 = A_bar^256 via 8 fp32 complex squarings
        float q0r = ab0x, q0i = ab0y, q1r = ab1x, q1i = ab1y;
        #pragma unroll
        for (int i = 0; i < 8; i++) {
            float n0r = q0r * q0r - q0i * q0i, n0i = 2.0f * q0r * q0i;
            float n1r = q1r * q1r - q1i * q1i, n1i = 2.0f * q1r * q1i;
            q0r = n0r; q0i = n0i; q1r = n1r; q1i = n1i;
        }

        // seed = A256^seg (binary exponentiation, 6 uniform steps)
        float vr0 = 1.0f, vi0 = 0.0f, vr1 = 1.0f, vi1 = 0.0f;
        #pragma unroll
        for (int b = 0; b < 6; b++) {
            if (seg & (1 << b)) {
                float t0r = vr0 * q0r - vi0 * q0i;
                float t0i = vr0 * q0i + vi0 * q0r;
                float t1r = vr1 * q1r - vi1 * q1i;
                float t1i = vr1 * q1i + vi1 * q1r;
                vr0 = t0r; vi0 = t0i; vr1 = t1r; vi1 = t1i;
            }
            if (b < 5) {
                float s0r = q0r * q0r - q0i * q0i, s0i = 2.0f * q0r * q0i;
                float s1r = q1r * q1r - q1i * q1i, s1i = 2.0f * q1r * q1i;
                q0r = s0r; q0i = s0i; q1r = s1r; q1i = s1i;
            }
        }

        __half2* b0p = (__half2*)g_B[0];
        __half2* b1p = (__half2*)g_B[1];
        int l0 = seg * 256;
        size_t base = ((size_t)pg * 16384 + l0) * 32 + lane;   // half2 units

        #pragma unroll 4
        for (int t = 0; t < 256; t++) {
            size_t o = base + (size_t)t * 32;
            b0p[o] = __floats2half2_rn(vr0, vr1);
            b1p[o] = __floats2half2_rn(vi0, vi1);
            float n0r = vr0 * ab0x - vi0 * ab0y;
            float n0i = vr0 * ab0y + vi0 * ab0x;
            float n1r = vr1 * ab1x - vi1 * ab1y;
            float n1i = vr1 * ab1y + vi1 * ab1x;
            vr0 = n0r; vi0 = n0i; vr1 = n1r; vi1 = n1i;
        }
    } else {
        __shared__ float2 scf[64];
        int b  = blockIdx.x - 128;      // 0..63
        int kc = b >> 2;                // 0..15
        int h0 = (b & 3) * 64;
        int t  = threadIdx.x;

        if (t < 64) {
            int p = kc * 64 + t;
            float ar = Ain[2 * p], ai = Ain[2 * p + 1];
            float abr, abi;
            abar_taylor(ar, ai, abr, abi);
            float nr = abr - 1.0f, ni = abi;       // Sterbenz-exact
            float den = ar * ar + ai * ai;
            scf[t] = make_float2((nr * ar + ni * ai) / den,
                                 (ni * ar - nr * ai) / den);
        }
        __syncthreads();

        int kk  = t & 63;
        int hh0 = t >> 6;               // 0..3
        int p   = kc * 64 + kk;
        float2 cf = scf[kk];

        #pragma unroll 4
        for (int i = 0; i < 16; i++) {
            int h = h0 + i * 4 + hh0;
            float br = B[(p * Hdim + h) * 2], bi = B[(p * Hdim + h) * 2 + 1];
            float bbr = cf.x * br - cf.y * bi;
            float bbi = cf.x * bi + cf.y * br;
            float cr = C[(h * Pdim + p) * 2], ci = C[(h * Pdim + p) * 2 + 1];
            float wr = (cr * bbr - ci * bbi) * WSCALE;
            float wi = (cr * bbi + ci * bbr) * WSCALE;

            size_t o = ((size_t)kc * 256 + h) * 64 + kk;
            g_A[0][o] = __float2half_rn(wr);
            g_A[1][o] = __float2half_rn(wi);
            g_A[2][o] = __float2half_rn(-wi);
        }
    }
}

// ---------------------------------------------------------------------------
// k_gemm: fused 4-mult complex GEMM, direct interleaved output.
//   accR += Wr*Vr + (-Wi)*Vi ;  accI += Wi*Vr + Wr*Vi
// CTA 128m x 128n, 512 thr (16 warps 4x4, warp 32x32), 2-stage cp.async.
// ---------------------------------------------------------------------------
__global__ __launch_bounds__(512, 1) void k_gemm(float* __restrict__ out) {
    extern __shared__ char smp[];
    const int tid  = threadIdx.x;
    const int lane = tid & 31;
    const int wid  = tid >> 5;
    const int wm   = wid >> 2;            // 0..3
    const int wn   = wid & 3;             // 0..3
    const int m0   = blockIdx.x * 128;
    const int n0   = blockIdx.y * 128;
    const uint32_t sb = s2u(smp);

    float accR[2][4][4], accI[2][4][4];
    #pragma unroll
    for (int i = 0; i < 2; i++)
        #pragma unroll
        for (int j = 0; j < 4; j++)
            #pragma unroll
            for (int t = 0; t < 4; t++) { accR[i][j][t] = 0.0f; accI[i][j][t] = 0.0f; }

    const int crow = tid >> 3;
    const int ccol = tid & 7;
    const uint32_t dA0 = sb + crow * 128 + ((ccol ^ (crow & 7)) << 4);
    const uint32_t dA1 = dA0 + STAGE_BYTES;
    const char* pA = (const char*)g_A[0] +
                     (((size_t)(m0 + crow) * 64 + ccol * 8) * 2);
    const char* pB = (const char*)g_B[0] +
                     (((size_t)(n0 + crow) * 64 + ccol * 8) * 2);

    auto issue = [&](uint32_t dA) {
        cpa<0,         0>(dA, pA);                 // Wr
        cpa<8192,   8192>(dA, pA);
        cpa<16384,     0>(dA, pA + 524288);        // Wi
        cpa<24576,  8192>(dA, pA + 524288);
        cpa<32768,     0>(dA, pA + 1048576);       // -Wi
        cpa<40960,  8192>(dA, pA + 1048576);
        cpa<49152,     0>(dA, pB);                 // Vr
        cpa<57344,  8192>(dA, pB);
        cpa<65536,     0>(dA, pB + 33554432);      // Vi
        cpa<73728,  8192>(dA, pB + 33554432);
        asm volatile("cp.async.commit_group;" ::: "memory");
        pA += 32768;
        pB += 2097152;
    };

    const int r15 = lane & 15, h16 = lane >> 4;
    const int rA = wm * 32 + r15;
    const int rB = wn * 32 + r15;
    uint32_t oA[4], oB[4];
    #pragma unroll
    for (int ks = 0; ks < 4; ks++) {
        const int cc = 2 * ks + h16;
        oA[ks] = (uint32_t)(rA * 128 + ((cc ^ (rA & 7)) << 4));
        oB[ks] = (uint32_t)(rB * 128 + ((cc ^ (rB & 7)) << 4)) + 49152u;
    }

    issue(dA0);

    #pragma unroll 2
    for (int k = 0; k < NKC; k++) {
        const uint32_t stage = sb + (uint32_t)((k & 1) * STAGE_BYTES);
        if (k + 1 < NKC) {
            issue((k & 1) ? dA0 : dA1);
            asm volatile("cp.async.wait_group 1;" ::: "memory");
        } else {
            asm volatile("cp.async.wait_group 0;" ::: "memory");
        }
        __syncthreads();

        #pragma unroll
        for (int ks = 0; ks < 4; ks++) {
            const uint32_t aAddr = stage + oA[ks];
            const uint32_t bAddr = stage + oB[ks];

            uint32_t ar0[4], ar1[4], ax0[4], ax1[4], b0[4], b1[4];
            // phase 1: Wr, Wi vs Vr
            ldm4<0>     (ar0, aAddr);
            ldm4<2048>  (ar1, aAddr);
            ldm4<16384> (ax0, aAddr);
            ldm4<18432> (ax1, aAddr);
            ldm4<0>     (b0, bAddr);
            ldm4<2048>  (b1, bAddr);

            mma16816(accR[0][0], ar0, b0[0], b0[2]);
            mma16816(accR[0][1], ar0, b0[1], b0[3]);
            mma16816(accR[0][2], ar0, b1[0], b1[2]);
            mma16816(accR[0][3], ar0, b1[1], b1[3]);
            mma16816(accR[1][0], ar1, b0[0], b0[2]);
            mma16816(accR[1][1], ar1, b0[1], b0[3]);
            mma16816(accR[1][2], ar1, b1[0], b1[2]);
            mma16816(accR[1][3], ar1, b1[1], b1[3]);
            mma16816(accI[0][0], ax0, b0[0], b0[2]);
            mma16816(accI[0][1], ax0, b0[1], b0[3]);
            mma16816(accI[0][2], ax0, b1[0], b1[2]);
            mma16816(accI[0][3], ax0, b1[1], b1[3]);
            mma16816(accI[1][0], ax1, b0[0], b0[2]);
            mma16816(accI[1][1], ax1, b0[1], b0[3]);
            mma16816(accI[1][2], ax1, b1[0], b1[2]);
            mma16816(accI[1][3], ax1, b1[1], b1[3]);

            // phase 2: reuse slots -> -Wi and Vi
            ldm4<32768> (ax0, aAddr);
            ldm4<34816> (ax1, aAddr);
            ldm4<16384> (b0, bAddr);
            ldm4<18432> (b1, bAddr);

            mma16816(accI[0][0], ar0, b0[0], b0[2]);
            mma16816(accI[0][1], ar0, b0[1], b0[3]);
            mma16816(accI[0][2], ar0, b1[0], b1[2]);
            mma16816(accI[0][3], ar0, b1[1], b1[3]);
            mma16816(accI[1][0], ar1, b0[0], b0[2]);
            mma16816(accI[1][1], ar1, b0[1], b0[3]);
            mma16816(accI[1][2], ar1, b1[0], b1[2]);
            mma16816(accI[1][3], ar1, b1[1], b1[3]);
            mma16816(accR[0][0], ax0, b0[0], b0[2]);
            mma16816(accR[0][1], ax0, b0[1], b0[3]);
            mma16816(accR[0][2], ax0, b1[0], b1[2]);
            mma16816(accR[0][3], ax0, b1[1], b1[3]);
            mma16816(accR[1][0], ax1, b0[0], b0[2]);
            mma16816(accR[1][1], ax1, b0[1], b0[3]);
            mma16816(accR[1][2], ax1, b1[0], b1[2]);
            mma16816(accR[1][3], ax1, b1[1], b1[3]);
        }
        __syncthreads();
    }

    // Epilogue: interleaved (re, im) float4 writes, n == l.
    const int mrow = lane >> 2, ncol = (lane & 3) * 2;
    #pragma unroll
    for (int im = 0; im < 2; im++) {
        int m = m0 + wm * 32 + im * 16 + mrow;
        #pragma unroll
        for (int jn = 0; jn < 4; jn++) {
            int n = n0 + wn * 32 + jn * 8 + ncol;
            float* p = out + ((size_t)m * Ldim + n) * 2;
            *(float4*)p = make_float4(accR[im][jn][0] * INV_WSCALE,
                                      accI[im][jn][0] * INV_WSCALE,
                                      accR[im][jn][1] * INV_WSCALE,
                                      accI[im][jn][1] * INV_WSCALE);
            *(float4*)(p + (size_t)16 * Ldim) = make_float4(
                                      accR[im][jn][2] * INV_WSCALE,
                                      accI[im][jn][2] * INV_WSCALE,
                                      accR[im][jn][3] * INV_WSCALE,
                                      accI[im][jn][3] * INV_WSCALE);
        }
    }
}

// ---------------------------------------------------------------------------
extern "C" void kernel_launch(void* const* d_in, const int* in_sizes, int n_in,
                              void* d_out, int out_size) {
    const float* A = (const float*)d_in[0];
    const float* B = (const float*)d_in[1];
    const float* C = (const float*)d_in[2];

    cudaFuncSetAttribute(k_gemm, cudaFuncAttributeMaxDynamicSharedMemorySize, 163840);

    k_fill<<<192, 256>>>(A, B, C);
    k_gemm<<<dim3(2, 128), 512, 163840>>>((float*)d_out);
}